// round 8
// baseline (speedup 1.0000x reference)
#include <cuda_runtime.h>
#include <math.h>

#define BATCH 128
#define SEQ   256
#define DIM   512
#define HID   1024
#define NCLS  128
#define NGATE 4
#define NJ    (HID * NGATE)   /* 4096 packed gate columns: jj = u*4 + gate */
#define NBLK  128             /* persistent CTAs (<= 148 SMs -> co-resident) */
#define NTHR  256
#define KT    32              /* K tile */

// ---------------- device scratch (globals: allocation-free) ----------------
__device__ float    g_Wpack[HID * NJ];        // [k][jj]  recurrent weights, gate-interleaved (16 MB)
__device__ float    g_Gpack[(NCLS + 1) * NJ]; // [tok][jj] input-side gate table (2.1 MB)
__device__ float    g_h[2][BATCH * HID];      // double-buffered hidden state
__device__ float    g_C[BATCH * HID];         // cell state
__device__ unsigned g_bar;                    // monotonic grid-barrier counter

// ---------------- init: zero state + barrier ----------------
__global__ void init_state_kernel() {
    int idx = blockIdx.x * blockDim.x + threadIdx.x;
    int n = BATCH * HID;
    for (int i = idx; i < n; i += gridDim.x * blockDim.x) {
        g_h[0][i] = 0.0f;
        g_C[i]    = 0.0f;
    }
    if (idx == 0) g_bar = 0u;
}

// ---------------- prepack recurrent weights: Wpack[k][u*4+g] = W{g}h[k][u] ----------------
__global__ void prepack_kernel(const float* __restrict__ Wfh, const float* __restrict__ Wih,
                               const float* __restrict__ Wgh, const float* __restrict__ Woh) {
    int idx = blockIdx.x * blockDim.x + threadIdx.x;
    if (idx >= HID * NJ) return;
    int k  = idx >> 12;       // / 4096
    int jj = idx & 4095;
    int g  = jj & 3;
    int u  = jj >> 2;
    const float* W = (g == 0) ? Wfh : (g == 1) ? Wih : (g == 2) ? Wgh : Woh;
    g_Wpack[idx] = W[k * HID + u];
}

// ---------------- input-side gate table: Gpack[c][u*4+g] = b_g[u] + emb[c] . W{g}x[:,u] ----------------
__global__ void gtable_kernel(const float* __restrict__ emb,
                              const float* __restrict__ Wfx, const float* __restrict__ Wix,
                              const float* __restrict__ Wgx, const float* __restrict__ Wox,
                              const float* __restrict__ bf,  const float* __restrict__ bi,
                              const float* __restrict__ bg,  const float* __restrict__ bo) {
    __shared__ float semb[DIM];
    int tid = threadIdx.x;                 // 128
    int jj  = blockIdx.x * 128 + tid;      // blockIdx.x in [0,32)
    int g   = jj & 3;
    int u   = jj >> 2;
    const float* W = (g == 0) ? Wfx : (g == 1) ? Wix : (g == 2) ? Wgx : Wox;
    float bias     = (g == 0) ? bf[u] : (g == 1) ? bi[u] : (g == 2) ? bg[u] : bo[u];

    int c0 = blockIdx.y * 26;
    int c1 = c0 + 26; if (c1 > NCLS + 1) c1 = NCLS + 1;
    for (int c = c0; c < c1; ++c) {
        for (int d = tid; d < DIM; d += 128) semb[d] = emb[c * DIM + d];
        __syncthreads();
        float acc = bias;
#pragma unroll 8
        for (int d = 0; d < DIM; ++d) acc = fmaf(semb[d], W[d * HID + u], acc);
        g_Gpack[c * NJ + jj] = acc;
        __syncthreads();
    }
}

// ---------------- persistent recurrence: 256 steps, one grid barrier per step ----------------
__global__ void __launch_bounds__(NTHR, 1)
lstm_recur_kernel(const int* __restrict__ x /* [BATCH][SEQ] */) {
    const int ci  = blockIdx.x;      // CTA owns hidden units u in [ci*8, ci*8+8), all 4 gates, all batches
    const int tid = threadIdx.x;
    const int cg    = tid & 15;      // column group: handles local cols cg and cg+16 (of 32)
    const int rbase = (tid >> 4) * 8;// row group: 8 consecutive batch rows

    __shared__ float sh[KT][132];    // transposed h tile: sh[k][b]
    __shared__ float sW[KT][33];     // weight tile: sW[k][lc]
    __shared__ float zbuf[BATCH][36];// pre-activations for epilogue regather

    const float* Wbase = g_Wpack + ci * 32;

    for (int t = 0; t < SEQ; ++t) {
        const float* hold = g_h[t & 1];
        float*       hnew = g_h[(t + 1) & 1];

        float acc[8][2];
#pragma unroll
        for (int r = 0; r < 8; ++r) { acc[r][0] = 0.0f; acc[r][1] = 0.0f; }

        for (int k0 = 0; k0 < HID; k0 += KT) {
            // load h tile (128 x 32), store transposed
#pragma unroll
            for (int q = 0; q < 4; ++q) {
                int idx = tid + q * 256;           // [0,1024)
                int b   = idx >> 3;                // [0,128)
                int kq  = idx & 7;                 // [0,8)
                float4 v = *(const float4*)&hold[b * HID + k0 + kq * 4];
                sh[kq * 4 + 0][b] = v.x;
                sh[kq * 4 + 1][b] = v.y;
                sh[kq * 4 + 2][b] = v.z;
                sh[kq * 4 + 3][b] = v.w;
            }
            // load W tile (32 x 32)
            {
                int kk = tid >> 3;
                int cq = (tid & 7) * 4;
                float4 w = *(const float4*)&Wbase[(size_t)(k0 + kk) * NJ + cq];
                sW[kk][cq + 0] = w.x;
                sW[kk][cq + 1] = w.y;
                sW[kk][cq + 2] = w.z;
                sW[kk][cq + 3] = w.w;
            }
            __syncthreads();
#pragma unroll
            for (int k = 0; k < KT; ++k) {
                float w0 = sW[k][cg];
                float w1 = sW[k][cg + 16];
                float4 ha = *(const float4*)&sh[k][rbase];
                float4 hb = *(const float4*)&sh[k][rbase + 4];
                acc[0][0] = fmaf(ha.x, w0, acc[0][0]); acc[0][1] = fmaf(ha.x, w1, acc[0][1]);
                acc[1][0] = fmaf(ha.y, w0, acc[1][0]); acc[1][1] = fmaf(ha.y, w1, acc[1][1]);
                acc[2][0] = fmaf(ha.z, w0, acc[2][0]); acc[2][1] = fmaf(ha.z, w1, acc[2][1]);
                acc[3][0] = fmaf(ha.w, w0, acc[3][0]); acc[3][1] = fmaf(ha.w, w1, acc[3][1]);
                acc[4][0] = fmaf(hb.x, w0, acc[4][0]); acc[4][1] = fmaf(hb.x, w1, acc[4][1]);
                acc[5][0] = fmaf(hb.y, w0, acc[5][0]); acc[5][1] = fmaf(hb.y, w1, acc[5][1]);
                acc[6][0] = fmaf(hb.z, w0, acc[6][0]); acc[6][1] = fmaf(hb.z, w1, acc[6][1]);
                acc[7][0] = fmaf(hb.w, w0, acc[7][0]); acc[7][1] = fmaf(hb.w, w1, acc[7][1]);
            }
            __syncthreads();
        }

        // scatter pre-activations so each thread can regather all 4 gates of one (b,u)
#pragma unroll
        for (int r = 0; r < 8; ++r) {
            zbuf[rbase + r][cg]      = acc[r][0];
            zbuf[rbase + r][cg + 16] = acc[r][1];
        }
        __syncthreads();

        // LSTM elementwise update: 128 batches x 8 units = 1024 items, 4 per thread
#pragma unroll
        for (int q = 0; q < 4; ++q) {
            int idx = tid + q * 256;
            int b   = idx >> 3;
            int ul  = idx & 7;
            int tok = x[b * SEQ + t];
            float4 gv = *(const float4*)&g_Gpack[(size_t)tok * NJ + (ci * 8 + ul) * 4];
            float zf = zbuf[b][ul * 4 + 0] + gv.x;
            float zi = zbuf[b][ul * 4 + 1] + gv.y;
            float zg = zbuf[b][ul * 4 + 2] + gv.z;
            float zo = zbuf[b][ul * 4 + 3] + gv.w;
            float f  = 1.0f / (1.0f + __expf(-zf));
            float ii = 1.0f / (1.0f + __expf(-zi));
            float gg = 1.0f / (1.0f + __expf(-zg));  // sigmoid per reference (not tanh)
            float oo = 1.0f / (1.0f + __expf(-zo));
            int   cidx = b * HID + ci * 8 + ul;
            float Cv   = g_C[cidx];
            float rst  = (tok > 0) ? 1.0f : 0.0f;
            Cv = (gg * ii + Cv * f) * rst;
            g_C[cidx]  = Cv;
            hnew[cidx] = oo * tanhf(Cv);
        }

        // grid barrier (monotonic counter; reset by init kernel each launch)
        __syncthreads();
        if (tid == 0) {
            __threadfence();
            atomicAdd(&g_bar, 1u);
            unsigned target = (unsigned)(t + 1) * (unsigned)NBLK;
            volatile unsigned* vb = &g_bar;
            while (*vb < target) { }
            __threadfence();
        }
        __syncthreads();
    }
}

// ---------------- final projection + log_softmax ----------------
__global__ void proj_softmax_kernel(const float* __restrict__ Wph, const float* __restrict__ bp,
                                    float* __restrict__ out) {
    __shared__ float shh[HID];
    __shared__ float red[NCLS];
    int b = blockIdx.x;
    int c = threadIdx.x;   // 128
    const float* hfin = g_h[0] + b * HID;   // SEQ=256 even -> final h lands in buffer 0
    for (int u = c; u < HID; u += NCLS) shh[u] = hfin[u];
    __syncthreads();

    float a0 = 0.f, a1 = 0.f, a2 = 0.f, a3 = 0.f;
    for (int u = 0; u < HID; u += 4) {
        a0 = fmaf(shh[u + 0], Wph[(u + 0) * NCLS + c], a0);
        a1 = fmaf(shh[u + 1], Wph[(u + 1) * NCLS + c], a1);
        a2 = fmaf(shh[u + 2], Wph[(u + 2) * NCLS + c], a2);
        a3 = fmaf(shh[u + 3], Wph[(u + 3) * NCLS + c], a3);
    }
    float acc = bp[c] + ((a0 + a1) + (a2 + a3));

    red[c] = acc; __syncthreads();
    for (int s = NCLS / 2; s > 0; s >>= 1) {
        if (c < s) red[c] = fmaxf(red[c], red[c + s]);
        __syncthreads();
    }
    float m = red[0]; __syncthreads();
    red[c] = __expf(acc - m); __syncthreads();
    for (int s = NCLS / 2; s > 0; s >>= 1) {
        if (c < s) red[c] += red[c + s];
        __syncthreads();
    }
    float lse = m + logf(red[0]);
    out[b * NCLS + c] = acc - lse;
}

// ---------------- launch ----------------
extern "C" void kernel_launch(void* const* d_in, const int* in_sizes, int n_in,
                              void* d_out, int out_size) {
    const int*   x   = (const int*)  d_in[0];
    const float* emb = (const float*)d_in[1];
    const float* Wfx = (const float*)d_in[2];
    const float* Wfh = (const float*)d_in[3];
    const float* bf  = (const float*)d_in[4];
    const float* Wix = (const float*)d_in[5];
    const float* Wih = (const float*)d_in[6];
    const float* bi  = (const float*)d_in[7];
    const float* Wgx = (const float*)d_in[8];
    const float* Wgh = (const float*)d_in[9];
    const float* bg  = (const float*)d_in[10];
    const float* Wox = (const float*)d_in[11];
    const float* Woh = (const float*)d_in[12];
    const float* bo  = (const float*)d_in[13];
    const float* Wph = (const float*)d_in[14];
    const float* bp  = (const float*)d_in[15];
    float* out = (float*)d_out;

    init_state_kernel<<<128, 256>>>();
    prepack_kernel<<<(HID * NJ + 255) / 256, 256>>>(Wfh, Wih, Wgh, Woh);
    dim3 gt_grid(32, 5);
    gtable_kernel<<<gt_grid, 128>>>(emb, Wfx, Wix, Wgx, Wox, bf, bi, bg, bo);
    lstm_recur_kernel<<<NBLK, NTHR>>>(x);
    proj_softmax_kernel<<<BATCH, NCLS>>>(Wph, bp, out);
}

// round 11
// speedup vs baseline: 3.0266x; 3.0266x over previous
#include <cuda_runtime.h>
#include <cuda_bf16.h>
#include <math.h>
#include <stdint.h>

#define BATCH 128
#define SEQ   256
#define DIM   512
#define HID   1024
#define NCLS  128
#define NJ    4096           /* packed gate cols: jj = u*4 + gate */
#define NBLK  128            /* persistent CTAs, one wave */
#define NTHR  256
#define NKB   64             /* k16 blocks over HID */
#define ZP    36             /* zbuf pitch in floats (16B-aligned rows) */

/* dynamic smem layout (bytes) */
#define SM_WH    0
#define SM_WL    65536
#define SM_ZB    131072
#define SM_BYTES (131072 + BATCH * ZP * 4)   /* 149504 */

// ---------------- device scratch (globals: allocation-free) ----------------
__device__ uint32_t g_Wfrag_hi[NBLK * NKB * 32 * 8];   // 8 MB, b-fragment order
__device__ uint32_t g_Wfrag_lo[NBLK * NKB * 32 * 8];   // 8 MB
__device__ float    g_Gpack[(NCLS + 1) * NJ];          // input-side gate table
__device__ uint32_t g_hfrag_hi[2][NKB * 8 * 32 * 4];   // h hi, a-fragment order, double-buffered
__device__ uint32_t g_hfrag_lo[2][NKB * 8 * 32 * 4];   // h lo residual
__device__ float    g_hfin[BATCH * HID];               // final fp32 h
__device__ unsigned g_bar;

// ---------------- mma.sync helper (sm_80+, no 'a' target needed) ----------------
__device__ __forceinline__ void mma16816(float* d,
                                         uint32_t a0, uint32_t a1, uint32_t a2, uint32_t a3,
                                         uint32_t b0, uint32_t b1) {
    asm volatile(
        "mma.sync.aligned.m16n8k16.row.col.f32.bf16.bf16.f32 "
        "{%0,%1,%2,%3}, {%4,%5,%6,%7}, {%8,%9}, {%0,%1,%2,%3};"
        : "+f"(d[0]), "+f"(d[1]), "+f"(d[2]), "+f"(d[3])
        : "r"(a0), "r"(a1), "r"(a2), "r"(a3), "r"(b0), "r"(b1));
}

__device__ __forceinline__ float sigmoidf_(float z) {
    return 1.0f / (1.0f + __expf(-z));
}

// ---------------- init: zero h buffer 0 + barrier ----------------
__global__ void init_state_kernel() {
    int idx = blockIdx.x * blockDim.x + threadIdx.x;
    int n = NKB * 8 * 32 * 4;
    for (int i = idx; i < n; i += gridDim.x * blockDim.x) {
        g_hfrag_hi[0][i] = 0u;
        g_hfrag_lo[0][i] = 0u;
    }
    if (idx == 0) g_bar = 0u;
}

// ---------------- prepack: W^T split bf16 in B-fragment order ----------------
// Linear u32 idx = ((ci*64 + kblk)*32 + lane)*8 + nt*2 + rb
// value = pack( W[k0][u], W[k0+1][u] ), k0 = kblk*16 + tig*2 + rb*8
// n = nt*8 + (lane>>2), jj = ci*32 + n, g = jj&3, u = jj>>2, tig = lane&3
__global__ void prepack_kernel(const float* __restrict__ Wfh, const float* __restrict__ Wih,
                               const float* __restrict__ Wgh, const float* __restrict__ Woh) {
    int idx = blockIdx.x * blockDim.x + threadIdx.x;
    if (idx >= NBLK * NKB * 32 * 8) return;
    int rb   = idx & 1;
    int nt   = (idx >> 1) & 3;
    int lane = (idx >> 3) & 31;
    int kblk = (idx >> 8) & 63;
    int ci   = idx >> 14;
    int n  = nt * 8 + (lane >> 2);
    int jj = ci * 32 + n;
    int g  = jj & 3;
    int u  = jj >> 2;
    int tig = lane & 3;
    int k0 = kblk * 16 + tig * 2 + rb * 8;
    const float* W = (g == 0) ? Wfh : (g == 1) ? Wih : (g == 2) ? Wgh : Woh;
    float w0 = W[k0 * HID + u];
    float w1 = W[(k0 + 1) * HID + u];
    __nv_bfloat16 h0 = __float2bfloat16(w0);
    __nv_bfloat16 h1 = __float2bfloat16(w1);
    __nv_bfloat16 l0 = __float2bfloat16(w0 - __bfloat162float(h0));
    __nv_bfloat16 l1 = __float2bfloat16(w1 - __bfloat162float(h1));
    g_Wfrag_hi[idx] = ((uint32_t)__bfloat16_as_ushort(h1) << 16) | __bfloat16_as_ushort(h0);
    g_Wfrag_lo[idx] = ((uint32_t)__bfloat16_as_ushort(l1) << 16) | __bfloat16_as_ushort(l0);
}

// ---------------- input-side gate table ----------------
__global__ void gtable_kernel(const float* __restrict__ emb,
                              const float* __restrict__ Wfx, const float* __restrict__ Wix,
                              const float* __restrict__ Wgx, const float* __restrict__ Wox,
                              const float* __restrict__ bf,  const float* __restrict__ bi,
                              const float* __restrict__ bg,  const float* __restrict__ bo) {
    __shared__ float semb[DIM];
    int tid = threadIdx.x;                 // 128
    int jj  = blockIdx.x * 128 + tid;
    int g   = jj & 3;
    int u   = jj >> 2;
    const float* W = (g == 0) ? Wfx : (g == 1) ? Wix : (g == 2) ? Wgx : Wox;
    float bias     = (g == 0) ? bf[u] : (g == 1) ? bi[u] : (g == 2) ? bg[u] : bo[u];
    int c0 = blockIdx.y * 26;
    int c1 = c0 + 26; if (c1 > NCLS + 1) c1 = NCLS + 1;
    for (int c = c0; c < c1; ++c) {
        for (int d = tid; d < DIM; d += 128) semb[d] = emb[c * DIM + d];
        __syncthreads();
        float acc = bias;
#pragma unroll 8
        for (int d = 0; d < DIM; ++d) acc = fmaf(semb[d], W[d * HID + u], acc);
        g_Gpack[c * NJ + jj] = acc;
        __syncthreads();
    }
}

// ---------------- persistent HMMA recurrence ----------------
__global__ void __launch_bounds__(NTHR, 1)
lstm_recur_kernel(const int* __restrict__ x /* [BATCH][SEQ] */) {
    extern __shared__ char smem[];
    float* zbuf = (float*)(smem + SM_ZB);
    const int tid  = threadIdx.x;
    const int wid  = tid >> 5;
    const int lane = tid & 31;
    const int ci   = blockIdx.x;

    // ---- load W slab (hi+lo, frag order, XOR bank swizzle) ----
    {
        const uint4* gh = (const uint4*)(g_Wfrag_hi + (size_t)ci * 16384);
        const uint4* gl = (const uint4*)(g_Wfrag_lo + (size_t)ci * 16384);
        for (int j = tid; j < 4096; j += NTHR) {
            int kb = j >> 6;
            int ln = (j >> 1) & 31;
            int h2 = j & 1;
            int fl = ((ln >> 2) & 1) << 4;
            int so = kb * 1024 + ln * 32 + (h2 ? (16 ^ fl) : fl);
            *(uint4*)(smem + SM_WH + so) = gh[j];
            *(uint4*)(smem + SM_WL + so) = gl[j];
        }
    }
    __syncthreads();

    const int flip = ((lane >> 2) & 1) << 4;
    float Creg[2][2] = {{0.f, 0.f}, {0.f, 0.f}};
    const int b0 = tid >> 2;            // epilogue item batches
    const int b1 = b0 + 64;
    const int tg = tid & 3;

    for (int t = 0; t < SEQ; ++t) {
        const int buf  = t & 1;
        const int nbuf = buf ^ 1;

        // prefetch tokens for this step (used in epilogue; overlaps mainloop)
        int tok0 = x[b0 * SEQ + t];
        int tok1 = x[b1 * SEQ + t];

        const uint4* AH = (const uint4*)g_hfrag_hi[buf];
        const uint4* AL = (const uint4*)g_hfrag_lo[buf];

        float d0[4], d1[4], d2[4], d3[4];
#pragma unroll
        for (int i = 0; i < 4; ++i) { d0[i] = 0.f; d1[i] = 0.f; d2[i] = 0.f; d3[i] = 0.f; }

        // depth-2 software pipeline on A
        uint4 pah[2], pal[2];
        pah[0] = AH[(0 * 8 + wid) * 32 + lane]; pal[0] = AL[(0 * 8 + wid) * 32 + lane];
        pah[1] = AH[(1 * 8 + wid) * 32 + lane]; pal[1] = AL[(1 * 8 + wid) * 32 + lane];

#pragma unroll 2
        for (int kb = 0; kb < NKB; ++kb) {
            uint4 ah = pah[kb & 1];
            uint4 al = pal[kb & 1];
            if (kb + 2 < NKB) {
                pah[kb & 1] = AH[((kb + 2) * 8 + wid) * 32 + lane];
                pal[kb & 1] = AL[((kb + 2) * 8 + wid) * 32 + lane];
            }
            const char* wb = smem + kb * 1024 + lane * 32;
            uint4 bh0 = *(const uint4*)(wb + SM_WH + flip);
            uint4 bh1 = *(const uint4*)(wb + SM_WH + (16 ^ flip));
            uint4 bl0 = *(const uint4*)(wb + SM_WL + flip);
            uint4 bl1 = *(const uint4*)(wb + SM_WL + (16 ^ flip));
            // hh @ Wh
            mma16816(d0, ah.x, ah.y, ah.z, ah.w, bh0.x, bh0.y);
            mma16816(d1, ah.x, ah.y, ah.z, ah.w, bh0.z, bh0.w);
            mma16816(d2, ah.x, ah.y, ah.z, ah.w, bh1.x, bh1.y);
            mma16816(d3, ah.x, ah.y, ah.z, ah.w, bh1.z, bh1.w);
            // hh @ Wl
            mma16816(d0, ah.x, ah.y, ah.z, ah.w, bl0.x, bl0.y);
            mma16816(d1, ah.x, ah.y, ah.z, ah.w, bl0.z, bl0.w);
            mma16816(d2, ah.x, ah.y, ah.z, ah.w, bl1.x, bl1.y);
            mma16816(d3, ah.x, ah.y, ah.z, ah.w, bl1.z, bl1.w);
            // hl @ Wh
            mma16816(d0, al.x, al.y, al.z, al.w, bh0.x, bh0.y);
            mma16816(d1, al.x, al.y, al.z, al.w, bh0.z, bh0.w);
            mma16816(d2, al.x, al.y, al.z, al.w, bh1.x, bh1.y);
            mma16816(d3, al.x, al.y, al.z, al.w, bh1.z, bh1.w);
        }

        // ---- scatter pre-activations to zbuf ----
        {
            int r0 = wid * 16 + (lane >> 2);
            int c0 = (lane & 3) * 2;
            float* zr0 = zbuf + r0 * ZP + c0;
            float* zr1 = zbuf + (r0 + 8) * ZP + c0;
            *(float2*)(zr0 + 0)  = make_float2(d0[0], d0[1]);
            *(float2*)(zr1 + 0)  = make_float2(d0[2], d0[3]);
            *(float2*)(zr0 + 8)  = make_float2(d1[0], d1[1]);
            *(float2*)(zr1 + 8)  = make_float2(d1[2], d1[3]);
            *(float2*)(zr0 + 16) = make_float2(d2[0], d2[1]);
            *(float2*)(zr1 + 16) = make_float2(d2[2], d2[3]);
            *(float2*)(zr0 + 24) = make_float2(d3[0], d3[1]);
            *(float2*)(zr1 + 24) = make_float2(d3[2], d3[3]);
        }
        __syncthreads();

        // ---- epilogue: 2 items per thread, each = 2 hidden units of one batch ----
        float4 z00 = *(const float4*)&zbuf[b0 * ZP + tg * 8];
        float4 z01 = *(const float4*)&zbuf[b0 * ZP + tg * 8 + 4];
        float4 z10 = *(const float4*)&zbuf[b1 * ZP + tg * 8];
        float4 z11 = *(const float4*)&zbuf[b1 * ZP + tg * 8 + 4];
        const float* gp0 = g_Gpack + (size_t)tok0 * NJ + ci * 32 + tg * 8;
        const float* gp1 = g_Gpack + (size_t)tok1 * NJ + ci * 32 + tg * 8;
        float4 g00 = *(const float4*)gp0;
        float4 g01 = *(const float4*)(gp0 + 4);
        float4 g10 = *(const float4*)gp1;
        float4 g11 = *(const float4*)(gp1 + 4);

        uint32_t* HH = g_hfrag_hi[nbuf];
        uint32_t* HL = g_hfrag_lo[nbuf];

#pragma unroll
        for (int q = 0; q < 2; ++q) {
            int    b   = q ? b1 : b0;
            int    tok = q ? tok1 : tok0;
            float4 za  = q ? z10 : z00;
            float4 zb  = q ? z11 : z01;
            float4 ga  = q ? g10 : g00;
            float4 gb  = q ? g11 : g01;
            float  r   = (tok > 0) ? 1.0f : 0.0f;

            float f0 = sigmoidf_(za.x + ga.x), i0 = sigmoidf_(za.y + ga.y);
            float gg0 = sigmoidf_(za.z + ga.z), o0 = sigmoidf_(za.w + ga.w);
            float C0 = (gg0 * i0 + Creg[q][0] * f0) * r;
            Creg[q][0] = C0;
            float h0 = o0 * tanhf(C0);

            float f1 = sigmoidf_(zb.x + gb.x), i1 = sigmoidf_(zb.y + gb.y);
            float gg1 = sigmoidf_(zb.z + gb.z), o1 = sigmoidf_(zb.w + gb.w);
            float C1 = (gg1 * i1 + Creg[q][1] * f1) * r;
            Creg[q][1] = C1;
            float h1 = o1 * tanhf(C1);

            __nv_bfloat16 h0h = __float2bfloat16(h0);
            __nv_bfloat16 h1h = __float2bfloat16(h1);
            __nv_bfloat16 h0l = __float2bfloat16(h0 - __bfloat162float(h0h));
            __nv_bfloat16 h1l = __float2bfloat16(h1 - __bfloat162float(h1h));
            uint32_t ph = ((uint32_t)__bfloat16_as_ushort(h1h) << 16) | __bfloat16_as_ushort(h0h);
            uint32_t pl = ((uint32_t)__bfloat16_as_ushort(h1l) << 16) | __bfloat16_as_ushort(h0l);

            int off = ((((ci >> 1) * 8 + (b >> 4)) * 32 + (b & 7) * 4 + tg) << 2)
                      + ((b >> 3) & 1) + ((ci & 1) << 1);
            HH[off] = ph;
            HL[off] = pl;
            if (t == SEQ - 1)
                *(float2*)&g_hfin[b * HID + ci * 8 + tg * 2] = make_float2(h0, h1);
        }

        // ---- grid barrier (monotonic counter; fence flushes/invalidates L1) ----
        __syncthreads();
        if (tid == 0) {
            __threadfence();
            atomicAdd(&g_bar, 1u);
            unsigned target = (unsigned)(t + 1) * (unsigned)NBLK;
            volatile unsigned* vb = &g_bar;
            while (*vb < target) { }
            __threadfence();
        }
        __syncthreads();
    }
}

// ---------------- final projection + log_softmax ----------------
__global__ void proj_softmax_kernel(const float* __restrict__ Wph, const float* __restrict__ bp,
                                    float* __restrict__ out) {
    __shared__ float shh[HID];
    __shared__ float red[NCLS];
    int b = blockIdx.x;
    int c = threadIdx.x;   // 128
    const float* hfin = g_hfin + (size_t)b * HID;
    for (int u = c; u < HID; u += NCLS) shh[u] = hfin[u];
    __syncthreads();

    float a0 = 0.f, a1 = 0.f, a2 = 0.f, a3 = 0.f;
    for (int u = 0; u < HID; u += 4) {
        a0 = fmaf(shh[u + 0], Wph[(u + 0) * NCLS + c], a0);
        a1 = fmaf(shh[u + 1], Wph[(u + 1) * NCLS + c], a1);
        a2 = fmaf(shh[u + 2], Wph[(u + 2) * NCLS + c], a2);
        a3 = fmaf(shh[u + 3], Wph[(u + 3) * NCLS + c], a3);
    }
    float acc = bp[c] + ((a0 + a1) + (a2 + a3));

    red[c] = acc; __syncthreads();
    for (int s = NCLS / 2; s > 0; s >>= 1) {
        if (c < s) red[c] = fmaxf(red[c], red[c + s]);
        __syncthreads();
    }
    float m = red[0]; __syncthreads();
    red[c] = __expf(acc - m); __syncthreads();
    for (int s = NCLS / 2; s > 0; s >>= 1) {
        if (c < s) red[c] += red[c + s];
        __syncthreads();
    }
    float lse = m + logf(red[0]);
    out[b * NCLS + c] = acc - lse;
}

// ---------------- launch ----------------
extern "C" void kernel_launch(void* const* d_in, const int* in_sizes, int n_in,
                              void* d_out, int out_size) {
    const int*   x   = (const int*)  d_in[0];
    const float* emb = (const float*)d_in[1];
    const float* Wfx = (const float*)d_in[2];
    const float* Wfh = (const float*)d_in[3];
    const float* bf  = (const float*)d_in[4];
    const float* Wix = (const float*)d_in[5];
    const float* Wih = (const float*)d_in[6];
    const float* bi  = (const float*)d_in[7];
    const float* Wgx = (const float*)d_in[8];
    const float* Wgh = (const float*)d_in[9];
    const float* bg  = (const float*)d_in[10];
    const float* Wox = (const float*)d_in[11];
    const float* Woh = (const float*)d_in[12];
    const float* bo  = (const float*)d_in[13];
    const float* Wph = (const float*)d_in[14];
    const float* bp  = (const float*)d_in[15];
    float* out = (float*)d_out;

    cudaFuncSetAttribute(lstm_recur_kernel,
                         cudaFuncAttributeMaxDynamicSharedMemorySize, SM_BYTES);

    init_state_kernel<<<128, 256>>>();
    prepack_kernel<<<(NBLK * NKB * 32 * 8 + 255) / 256, 256>>>(Wfh, Wih, Wgh, Woh);
    dim3 gt_grid(32, 5);
    gtable_kernel<<<gt_grid, 128>>>(emb, Wfx, Wix, Wgx, Wox, bf, bi, bg, bo);
    lstm_recur_kernel<<<NBLK, NTHR, SM_BYTES>>>(x);
    proj_softmax_kernel<<<BATCH, NCLS>>>(Wph, bp, out);
}